// round 7
// baseline (speedup 1.0000x reference)
#include <cuda_runtime.h>
#include <cuda_bf16.h>
#include <math.h>
#include <stdint.h>

// Problem constants
#define TT 128
#define BB 32
#define VV 10000
#define HH 1024
#define M1 (TT*BB)          // 4096
#define BH (BB*HH)          // 32768

#define RBLK 128            // persistent recurrence blocks (<=148: all resident)
#define RTHR 512

// ---------------- scratch (device globals; no allocation allowed) ----------
__device__ float g_Xz[M1*HH];
__device__ float g_Xr[M1*HH];
__device__ float g_Xh[M1*HH];
__device__ float g_Hs[TT*BB*HH];
__device__ float g_Z[BH];
__device__ float g_G[BH];
__device__ float g_WzT[HH*HH];
__device__ float g_WrT[HH*HH];
__device__ float g_WhT[HH*HH];
__device__ unsigned g_bar[2*TT];

// ---------------- cp.async helpers -----------------------------------------
__device__ __forceinline__ uint32_t smem_u32(const void* p) {
    return (uint32_t)__cvta_generic_to_shared(p);
}
#define CP_ASYNC16_CG(dst, src) \
    asm volatile("cp.async.cg.shared.global [%0], [%1], 16;\n" :: "r"(dst), "l"(src))
#define CP_ASYNC16_CA(dst, src) \
    asm volatile("cp.async.ca.shared.global [%0], [%1], 16;\n" :: "r"(dst), "l"(src))
#define CP_COMMIT() asm volatile("cp.async.commit_group;\n" ::: "memory")
#define CP_WAIT(n)  asm volatile("cp.async.wait_group %0;\n" :: "n"(n) : "memory")

// ============================================================================
// TF32 tensor-core GEMM (unchanged)
// ============================================================================
#define GBM 128
#define GBN 128
#define GBK 16

__device__ __forceinline__ uint32_t f2tf32(float f) {
    uint32_t u;
    asm("cvt.rna.tf32.f32 %0, %1;" : "=r"(u) : "f"(f));
    return u;
}

__device__ __forceinline__ void mma_tf32(float c[4], const uint32_t a[4],
                                         const uint32_t b[2]) {
    asm volatile(
        "mma.sync.aligned.m16n8k8.row.col.f32.tf32.tf32.f32 "
        "{%0,%1,%2,%3}, {%4,%5,%6,%7}, {%8,%9}, {%0,%1,%2,%3};\n"
        : "+f"(c[0]), "+f"(c[1]), "+f"(c[2]), "+f"(c[3])
        : "r"(a[0]), "r"(a[1]), "r"(a[2]), "r"(a[3]), "r"(b[0]), "r"(b[1]));
}

__global__ __launch_bounds__(256)
void tf32_gemm_bias(const float* __restrict__ A, const float* __restrict__ B,
                    const float* __restrict__ bias, float* __restrict__ C,
                    int M, int N, int K)
{
    __shared__ uint32_t As[GBM][GBK + 4];
    __shared__ uint32_t Bs[GBK][GBN + 8];

    const int tid  = threadIdx.x;
    const int wid  = tid >> 5;
    const int lane = tid & 31;
    const int m0 = blockIdx.y * GBM;
    const int n0 = blockIdx.x * GBN;

    const int wm = (wid & 3) * 32;
    const int wn = (wid >> 2) * 64;
    const int g  = lane >> 2;
    const int tg = lane & 3;

    float c[2][8][4];
#pragma unroll
    for (int mt = 0; mt < 2; ++mt)
#pragma unroll
        for (int nt = 0; nt < 8; ++nt)
#pragma unroll
            for (int i = 0; i < 4; ++i) c[mt][nt][i] = 0.f;

    float4 avr[2], bvr[2];

    auto loadA = [&](int kc) {
#pragma unroll
        for (int i = 0; i < 2; ++i) {
            int s = tid + i * 256;
            avr[i] = *(const float4*)&A[(size_t)(m0 + (s >> 2)) * K + kc + (s & 3) * 4];
        }
    };
    auto loadB = [&](int kc) {
#pragma unroll
        for (int i = 0; i < 2; ++i) {
            int s = tid + i * 256;
            int col = n0 + (s & 31) * 4;
            if (col + 3 < N)
                bvr[i] = *(const float4*)&B[(size_t)(kc + (s >> 5)) * N + col];
            else
                bvr[i] = make_float4(0.f, 0.f, 0.f, 0.f);
        }
    };

    loadA(0);
    loadB(0);

    for (int kc = 0; kc < K; kc += GBK) {
        __syncthreads();
#pragma unroll
        for (int i = 0; i < 2; ++i) {
            int s = tid + i * 256;
            uint32_t* p = &As[s >> 2][(s & 3) * 4];
            p[0] = f2tf32(avr[i].x); p[1] = f2tf32(avr[i].y);
            p[2] = f2tf32(avr[i].z); p[3] = f2tf32(avr[i].w);
        }
#pragma unroll
        for (int i = 0; i < 2; ++i) {
            int s = tid + i * 256;
            uint32_t* p = &Bs[s >> 5][(s & 31) * 4];
            p[0] = f2tf32(bvr[i].x); p[1] = f2tf32(bvr[i].y);
            p[2] = f2tf32(bvr[i].z); p[3] = f2tf32(bvr[i].w);
        }
        __syncthreads();

        if (kc + GBK < K) {
            loadA(kc + GBK);
            loadB(kc + GBK);
        }

#pragma unroll
        for (int k8 = 0; k8 < GBK; k8 += 8) {
            uint32_t af[2][4];
#pragma unroll
            for (int mt = 0; mt < 2; ++mt) {
                int ra = wm + mt * 16 + g;
                af[mt][0] = As[ra][k8 + tg];
                af[mt][1] = As[ra + 8][k8 + tg];
                af[mt][2] = As[ra][k8 + tg + 4];
                af[mt][3] = As[ra + 8][k8 + tg + 4];
            }
            uint32_t bf[8][2];
#pragma unroll
            for (int nt = 0; nt < 8; ++nt) {
                int cn = wn + nt * 8 + g;
                bf[nt][0] = Bs[k8 + tg][cn];
                bf[nt][1] = Bs[k8 + tg + 4][cn];
            }
#pragma unroll
            for (int mt = 0; mt < 2; ++mt)
#pragma unroll
                for (int nt = 0; nt < 8; ++nt)
                    mma_tf32(c[mt][nt], af[mt], bf[nt]);
        }
    }

#pragma unroll
    for (int mt = 0; mt < 2; ++mt) {
        int row = m0 + wm + mt * 16 + g;
#pragma unroll
        for (int nt = 0; nt < 8; ++nt) {
            int col = n0 + wn + nt * 8 + tg * 2;
            if (col < N) {
                float2 bb = *(const float2*)&bias[col];
                float2 v0 = make_float2(c[mt][nt][0] + bb.x, c[mt][nt][1] + bb.y);
                float2 v1 = make_float2(c[mt][nt][2] + bb.x, c[mt][nt][3] + bb.y);
                *(float2*)&C[(size_t)row * N + col] = v0;
                *(float2*)&C[(size_t)(row + 8) * N + col] = v1;
            }
        }
    }
}

// ============================================================================
// 1024x1024 transpose (tiled, conflict-free): out[c][k] = in[k][c]
// ============================================================================
__global__ __launch_bounds__(256)
void transpose1024(const float* __restrict__ in, float* __restrict__ out)
{
    __shared__ float t[32][33];
    int x = blockIdx.x * 32 + threadIdx.x;
    int y0 = blockIdx.y * 32 + threadIdx.y;
#pragma unroll
    for (int j = 0; j < 32; j += 8)
        t[threadIdx.y + j][threadIdx.x] = in[(size_t)(y0 + j) * HH + x];
    __syncthreads();
    int xo = blockIdx.y * 32 + threadIdx.x;
    int yo = blockIdx.x * 32 + threadIdx.y;
#pragma unroll
    for (int j = 0; j < 32; j += 8)
        out[(size_t)(yo + j) * HH + xo] = t[threadIdx.x][threadIdx.y + j];
}

// ============================================================================
// Persistent GRU recurrence: 128 blocks x 512 threads, software grid barrier
// with PROPER release/acquire semantics (the R5 bug: relaxed arrive + relaxed
// spin gave no ordering for subsequent data loads -> stale reads).
// ============================================================================
__global__ void bar_init()
{
    int i = threadIdx.x;
    if (i < 2 * TT) g_bar[i] = 0u;
}

__device__ __forceinline__ void grid_bar(int idx)
{
    __threadfence();          // release own writes (all threads)
    __syncthreads();          // block-local order before arrive
    if (threadIdx.x == 0) {
        unsigned prev;
        asm volatile("atom.add.release.gpu.global.u32 %0, [%1], 1;"
                     : "=r"(prev) : "l"(&g_bar[idx]) : "memory");
        unsigned v;
        do {
            asm volatile("ld.acquire.gpu.global.u32 %0, [%1];"
                         : "=r"(v) : "l"(&g_bar[idx]) : "memory");
        } while (v < RBLK);
        __threadfence();      // acquire-side fence: order data loads after spin
    }
    __syncthreads();          // propagate acquire to whole block
}

__device__ __forceinline__ float sigf(float x) {
    return 1.f / (1.f + __expf(-x));
}

// smem pool layout (floats), KC = 64, row stride 68:
//  phase1: Hp[buf][32][68] at 0 (4352), Wt[buf][16][68] at 4352 (2176) -> 6528
//  phase2: Gp[buf][half][32][68] at 0 (8704), W2[buf][half][8][68] at 8704 (2176)
//  red[256] at 10880
#define RKC 64
#define RST 68
#define POOLF (10880 + 256)

__global__ __launch_bounds__(RTHR, 1)
void gru_persistent(const float* __restrict__ H0,
                    const float* __restrict__ Xz, const float* __restrict__ Xr,
                    const float* __restrict__ Xh,
                    const float* __restrict__ WzT, const float* __restrict__ WrT,
                    const float* __restrict__ WhT,
                    float* __restrict__ Hs, float* __restrict__ Z,
                    float* __restrict__ G)
{
    __shared__ float pool[POOLF];

    const int tid = threadIdx.x;
    const int blk = blockIdx.x;

    // phase1 mapping
    const bool isR = blk >= 64;
    const int c1 = (blk & 63) * 16;            // 16 cols of z or r
    const int b1 = tid >> 4;                   // 0..31
    const int cc1 = tid & 15;                  // 0..15
    const float* __restrict__ W1 = isR ? WrT : WzT;

    // phase2 mapping
    const int c2 = blk * 8;                    // 8 cols
    const int out2 = tid & 255;
    const int b2 = out2 >> 3;
    const int cc2 = out2 & 7;
    const int kh = tid >> 8;                   // 0/1 : k half

    for (int t = 0; t < TT; ++t) {
        const float* __restrict__ Hprev = (t == 0) ? H0 : (Hs + (size_t)(t - 1) * BH);
        const float* __restrict__ Xz_t = Xz + (size_t)t * BH;
        const float* __restrict__ Xr_t = Xr + (size_t)t * BH;
        const float* __restrict__ Xh_t = Xh + (size_t)t * BH;
        float* __restrict__ Hnew = Hs + (size_t)t * BH;

        // ---------------- phase 1: Z (blocks 0-63) / R,G (blocks 64-127) ----
        {
            float4 acc = make_float4(0.f, 0.f, 0.f, 0.f);

            auto load1 = [&](int buf, int kc) {
                // Hp: 32 x 64 floats = 512 float4, one per thread
                {
                    int row = tid >> 4, q = tid & 15;
                    uint32_t d = smem_u32(&pool[buf * 2176 + row * RST + q * 4]);
                    CP_ASYNC16_CG(d, &Hprev[row * HH + kc + q * 4]);
                }
                // Wt: 16 x 64 = 256 float4, threads < 256
                if (tid < 256) {
                    int row = tid >> 4, q = tid & 15;
                    uint32_t d = smem_u32(&pool[4352 + buf * 1088 + row * RST + q * 4]);
                    CP_ASYNC16_CA(d, &W1[(size_t)(c1 + row) * HH + kc + q * 4]);
                }
                CP_COMMIT();
            };

            load1(0, 0);
#pragma unroll 1
            for (int c = 0; c < HH / RKC; ++c) {
                if (c + 1 < HH / RKC) {
                    load1((c + 1) & 1, (c + 1) * RKC);
                    CP_WAIT(1);
                } else {
                    CP_WAIT(0);
                }
                __syncthreads();
                const int buf = c & 1;
                const float* hp = &pool[buf * 2176 + b1 * RST];
                const float* wp = &pool[4352 + buf * 1088 + cc1 * RST];
#pragma unroll
                for (int kk = 0; kk < RKC; kk += 4) {
                    float4 h = *(const float4*)&hp[kk];
                    float4 w = *(const float4*)&wp[kk];
                    acc.x += h.x * w.x; acc.y += h.y * w.y;
                    acc.z += h.z * w.z; acc.w += h.w * w.w;
                }
                __syncthreads();
            }

            float s = (acc.x + acc.y) + (acc.z + acc.w);
            const int i0 = b1 * HH + c1 + cc1;
            if (!isR) {
                __stcg(&Z[i0], sigf(Xz_t[i0] + s));
            } else {
                float r = sigf(Xr_t[i0] + s);
                __stcg(&G[i0], r * __ldcg(&Hprev[i0]));
            }
        }

        grid_bar(2 * t);

        // ---------------- phase 2: Hnew --------------------------------------
        {
            float4 acc = make_float4(0.f, 0.f, 0.f, 0.f);

            auto load2 = [&](int buf, int c) {
                // Gp: 2 halves x 32 x 64 = 1024 float4 -> 2 per thread
#pragma unroll
                for (int i = 0; i < 2; ++i) {
                    int s = tid + i * 512;
                    int half = s >> 9, rr = (s >> 4) & 31, q = s & 15;
                    uint32_t d = smem_u32(&pool[buf * 4352 + half * 2176 + rr * RST + q * 4]);
                    CP_ASYNC16_CG(d, &G[rr * HH + half * 512 + c * RKC + q * 4]);
                }
                // W2: 2 halves x 8 x 64 = 256 float4 -> threads < 256
                if (tid < 256) {
                    int half = tid >> 7, rr = (tid >> 4) & 7, q = tid & 15;
                    uint32_t d = smem_u32(&pool[8704 + buf * 1088 + half * 544 + rr * RST + q * 4]);
                    CP_ASYNC16_CA(d, &WhT[(size_t)(c2 + rr) * HH + half * 512 + c * RKC + q * 4]);
                }
                CP_COMMIT();
            };

            load2(0, 0);
#pragma unroll 1
            for (int c = 0; c < 512 / RKC; ++c) {
                if (c + 1 < 512 / RKC) {
                    load2((c + 1) & 1, c + 1);
                    CP_WAIT(1);
                } else {
                    CP_WAIT(0);
                }
                __syncthreads();
                const int buf = c & 1;
                const float* gp = &pool[buf * 4352 + kh * 2176 + b2 * RST];
                const float* wp = &pool[8704 + buf * 1088 + kh * 544 + cc2 * RST];
#pragma unroll
                for (int kk = 0; kk < RKC; kk += 4) {
                    float4 g4 = *(const float4*)&gp[kk];
                    float4 w = *(const float4*)&wp[kk];
                    acc.x += g4.x * w.x; acc.y += g4.y * w.y;
                    acc.z += g4.z * w.z; acc.w += g4.w * w.w;
                }
                __syncthreads();
            }

            float s = (acc.x + acc.y) + (acc.z + acc.w);
            if (kh == 1) pool[10880 + out2] = s;
            __syncthreads();
            if (kh == 0) {
                s += pool[10880 + out2];
                const int i0 = b2 * HH + c2 + cc2;
                float ht = tanhf(Xh_t[i0] + s);
                float z = __ldcg(&Z[i0]);
                float hp = __ldcg(&Hprev[i0]);
                __stcg(&Hnew[i0], z * hp + (1.f - z) * ht);
            }
        }

        grid_bar(2 * t + 1);
    }
}

// ---------------- H_last copy ----------------------------------------------
__global__ void copy_hlast(const float* __restrict__ src, float* __restrict__ dst)
{
    int i = blockIdx.x * blockDim.x + threadIdx.x;
    if (i < BH) dst[i] = src[i];
}

// ---------------- launch ----------------------------------------------------
extern "C" void kernel_launch(void* const* d_in, const int* in_sizes, int n_in,
                              void* d_out, int out_size)
{
    const float* inputs = (const float*)d_in[0];
    const float* H0     = (const float*)d_in[1];
    const float* W_xz   = (const float*)d_in[2];
    const float* W_hz   = (const float*)d_in[3];
    const float* b_z    = (const float*)d_in[4];
    const float* W_xr   = (const float*)d_in[5];
    const float* W_hr   = (const float*)d_in[6];
    const float* b_r    = (const float*)d_in[7];
    const float* W_xh   = (const float*)d_in[8];
    const float* W_hh   = (const float*)d_in[9];
    const float* b_h    = (const float*)d_in[10];
    const float* W_hq   = (const float*)d_in[11];
    const float* b_q    = (const float*)d_in[12];

    float* out = (float*)d_out;

    float *Xz, *Xr, *Xh, *Hs, *Zb, *Gb, *WzT, *WrT, *WhT;
    cudaGetSymbolAddress((void**)&Xz, g_Xz);
    cudaGetSymbolAddress((void**)&Xr, g_Xr);
    cudaGetSymbolAddress((void**)&Xh, g_Xh);
    cudaGetSymbolAddress((void**)&Hs, g_Hs);
    cudaGetSymbolAddress((void**)&Zb, g_Z);
    cudaGetSymbolAddress((void**)&Gb, g_G);
    cudaGetSymbolAddress((void**)&WzT, g_WzT);
    cudaGetSymbolAddress((void**)&WrT, g_WrT);
    cudaGetSymbolAddress((void**)&WhT, g_WhT);

    // 0) transpose recurrent weights + zero grid-barrier counters
    {
        dim3 tg(32, 32), tb(32, 8);
        transpose1024<<<tg, tb>>>(W_hz, WzT);
        transpose1024<<<tg, tb>>>(W_hr, WrT);
        transpose1024<<<tg, tb>>>(W_hh, WhT);
        bar_init<<<1, 256>>>();
    }

    // 1) input projections (TF32 tensor cores)
    {
        dim3 grid(HH / GBN, M1 / GBM);
        tf32_gemm_bias<<<grid, 256>>>(inputs, W_xz, b_z, Xz, M1, HH, VV);
        tf32_gemm_bias<<<grid, 256>>>(inputs, W_xr, b_r, Xr, M1, HH, VV);
        tf32_gemm_bias<<<grid, 256>>>(inputs, W_xh, b_h, Xh, M1, HH, VV);
    }

    // 2) recurrence: ONE persistent kernel, software grid barriers
    gru_persistent<<<RBLK, RTHR>>>(H0, Xz, Xr, Xh, WzT, WrT, WhT, Hs, Zb, Gb);

    // 3) output projection (TF32)
    {
        dim3 grid((VV + GBN - 1) / GBN, M1 / GBM);
        tf32_gemm_bias<<<grid, 256>>>(Hs, W_hq, b_q, out, M1, VV, HH);
    }

    // 4) H_last appended after outputs if the output buffer includes it
    if (out_size >= M1 * VV + BH) {
        copy_hlast<<<BH / 256, 256>>>(Hs + (size_t)(TT - 1) * BH,
                                      out + (size_t)M1 * VV);
    }
}

// round 8
// speedup vs baseline: 1.1706x; 1.1706x over previous
#include <cuda_runtime.h>
#include <cuda_bf16.h>
#include <math.h>
#include <stdint.h>

// Problem constants
#define TT 128
#define BB 32
#define VV 10000
#define HH 1024
#define M1 (TT*BB)          // 4096
#define BH (BB*HH)          // 32768

#define RBLK 128            // persistent recurrence blocks (<=148: all resident)
#define RTHR 512

// ---------------- scratch (device globals; no allocation allowed) ----------
__device__ float g_Xz[M1*HH];
__device__ float g_Xr[M1*HH];
__device__ float g_Xh[M1*HH];
__device__ float g_Hs[TT*BB*HH];
__device__ float g_Z[BH];
__device__ float g_G[BH];
__device__ float g_WzT[HH*HH];
__device__ float g_WrT[HH*HH];
__device__ float g_WhT[HH*HH];
__device__ unsigned g_bar[2*TT];

// ---------------- cp.async helpers -----------------------------------------
__device__ __forceinline__ uint32_t smem_u32(const void* p) {
    return (uint32_t)__cvta_generic_to_shared(p);
}
#define CP_ASYNC16_CG(dst, src) \
    asm volatile("cp.async.cg.shared.global [%0], [%1], 16;\n" :: "r"(dst), "l"(src))
#define CP_ASYNC16_CA(dst, src) \
    asm volatile("cp.async.ca.shared.global [%0], [%1], 16;\n" :: "r"(dst), "l"(src))
#define CP_COMMIT() asm volatile("cp.async.commit_group;\n" ::: "memory")
#define CP_WAIT(n)  asm volatile("cp.async.wait_group %0;\n" :: "n"(n) : "memory")

// ============================================================================
// TF32 tensor-core GEMM (unchanged)
// ============================================================================
#define GBM 128
#define GBN 128
#define GBK 16

__device__ __forceinline__ uint32_t f2tf32(float f) {
    uint32_t u;
    asm("cvt.rna.tf32.f32 %0, %1;" : "=r"(u) : "f"(f));
    return u;
}

__device__ __forceinline__ void mma_tf32(float c[4], const uint32_t a[4],
                                         const uint32_t b[2]) {
    asm volatile(
        "mma.sync.aligned.m16n8k8.row.col.f32.tf32.tf32.f32 "
        "{%0,%1,%2,%3}, {%4,%5,%6,%7}, {%8,%9}, {%0,%1,%2,%3};\n"
        : "+f"(c[0]), "+f"(c[1]), "+f"(c[2]), "+f"(c[3])
        : "r"(a[0]), "r"(a[1]), "r"(a[2]), "r"(a[3]), "r"(b[0]), "r"(b[1]));
}

__global__ __launch_bounds__(256)
void tf32_gemm_bias(const float* __restrict__ A, const float* __restrict__ B,
                    const float* __restrict__ bias, float* __restrict__ C,
                    int M, int N, int K)
{
    __shared__ uint32_t As[GBM][GBK + 4];
    __shared__ uint32_t Bs[GBK][GBN + 8];

    const int tid  = threadIdx.x;
    const int wid  = tid >> 5;
    const int lane = tid & 31;
    const int m0 = blockIdx.y * GBM;
    const int n0 = blockIdx.x * GBN;

    const int wm = (wid & 3) * 32;
    const int wn = (wid >> 2) * 64;
    const int g  = lane >> 2;
    const int tg = lane & 3;

    float c[2][8][4];
#pragma unroll
    for (int mt = 0; mt < 2; ++mt)
#pragma unroll
        for (int nt = 0; nt < 8; ++nt)
#pragma unroll
            for (int i = 0; i < 4; ++i) c[mt][nt][i] = 0.f;

    float4 avr[2], bvr[2];

    auto loadA = [&](int kc) {
#pragma unroll
        for (int i = 0; i < 2; ++i) {
            int s = tid + i * 256;
            avr[i] = *(const float4*)&A[(size_t)(m0 + (s >> 2)) * K + kc + (s & 3) * 4];
        }
    };
    auto loadB = [&](int kc) {
#pragma unroll
        for (int i = 0; i < 2; ++i) {
            int s = tid + i * 256;
            int col = n0 + (s & 31) * 4;
            if (col + 3 < N)
                bvr[i] = *(const float4*)&B[(size_t)(kc + (s >> 5)) * N + col];
            else
                bvr[i] = make_float4(0.f, 0.f, 0.f, 0.f);
        }
    };

    loadA(0);
    loadB(0);

    for (int kc = 0; kc < K; kc += GBK) {
        __syncthreads();
#pragma unroll
        for (int i = 0; i < 2; ++i) {
            int s = tid + i * 256;
            uint32_t* p = &As[s >> 2][(s & 3) * 4];
            p[0] = f2tf32(avr[i].x); p[1] = f2tf32(avr[i].y);
            p[2] = f2tf32(avr[i].z); p[3] = f2tf32(avr[i].w);
        }
#pragma unroll
        for (int i = 0; i < 2; ++i) {
            int s = tid + i * 256;
            uint32_t* p = &Bs[s >> 5][(s & 31) * 4];
            p[0] = f2tf32(bvr[i].x); p[1] = f2tf32(bvr[i].y);
            p[2] = f2tf32(bvr[i].z); p[3] = f2tf32(bvr[i].w);
        }
        __syncthreads();

        if (kc + GBK < K) {
            loadA(kc + GBK);
            loadB(kc + GBK);
        }

#pragma unroll
        for (int k8 = 0; k8 < GBK; k8 += 8) {
            uint32_t af[2][4];
#pragma unroll
            for (int mt = 0; mt < 2; ++mt) {
                int ra = wm + mt * 16 + g;
                af[mt][0] = As[ra][k8 + tg];
                af[mt][1] = As[ra + 8][k8 + tg];
                af[mt][2] = As[ra][k8 + tg + 4];
                af[mt][3] = As[ra + 8][k8 + tg + 4];
            }
            uint32_t bf[8][2];
#pragma unroll
            for (int nt = 0; nt < 8; ++nt) {
                int cn = wn + nt * 8 + g;
                bf[nt][0] = Bs[k8 + tg][cn];
                bf[nt][1] = Bs[k8 + tg + 4][cn];
            }
#pragma unroll
            for (int mt = 0; mt < 2; ++mt)
#pragma unroll
                for (int nt = 0; nt < 8; ++nt)
                    mma_tf32(c[mt][nt], af[mt], bf[nt]);
        }
    }

#pragma unroll
    for (int mt = 0; mt < 2; ++mt) {
        int row = m0 + wm + mt * 16 + g;
#pragma unroll
        for (int nt = 0; nt < 8; ++nt) {
            int col = n0 + wn + nt * 8 + tg * 2;
            if (col < N) {
                float2 bb = *(const float2*)&bias[col];
                float2 v0 = make_float2(c[mt][nt][0] + bb.x, c[mt][nt][1] + bb.y);
                float2 v1 = make_float2(c[mt][nt][2] + bb.x, c[mt][nt][3] + bb.y);
                *(float2*)&C[(size_t)row * N + col] = v0;
                *(float2*)&C[(size_t)(row + 8) * N + col] = v1;
            }
        }
    }
}

// ============================================================================
// 1024x1024 transpose (tiled, conflict-free): out[c][k] = in[k][c]
// ============================================================================
__global__ __launch_bounds__(256)
void transpose1024(const float* __restrict__ in, float* __restrict__ out)
{
    __shared__ float t[32][33];
    int x = blockIdx.x * 32 + threadIdx.x;
    int y0 = blockIdx.y * 32 + threadIdx.y;
#pragma unroll
    for (int j = 0; j < 32; j += 8)
        t[threadIdx.y + j][threadIdx.x] = in[(size_t)(y0 + j) * HH + x];
    __syncthreads();
    int xo = blockIdx.y * 32 + threadIdx.x;
    int yo = blockIdx.x * 32 + threadIdx.y;
#pragma unroll
    for (int j = 0; j < 32; j += 8)
        out[(size_t)(yo + j) * HH + xo] = t[threadIdx.x][threadIdx.y + j];
}

// ============================================================================
// Persistent GRU recurrence v2: proven release/acquire barrier (R6) + NEW
// compute mapping: thread = (lane=batch, warp=(colgroup, kslice)) so W
// fragments broadcast across the warp and FFMA is the binding pipe.
// ============================================================================
__global__ void bar_init()
{
    int i = threadIdx.x;
    if (i < 2 * TT) g_bar[i] = 0u;
}

__device__ __forceinline__ void grid_bar(int idx)
{
    __threadfence();
    __syncthreads();
    if (threadIdx.x == 0) {
        unsigned prev;
        asm volatile("atom.add.release.gpu.global.u32 %0, [%1], 1;"
                     : "=r"(prev) : "l"(&g_bar[idx]) : "memory");
        unsigned v;
        do {
            asm volatile("ld.acquire.gpu.global.u32 %0, [%1];"
                         : "=r"(v) : "l"(&g_bar[idx]) : "memory");
        } while (v < RBLK);
        __threadfence();
    }
    __syncthreads();
}

__device__ __forceinline__ float sigf(float x) {
    return 1.f / (1.f + __expf(-x));
}

// smem pool (floats), KC=64, row stride 68:
//  Hp/Gp[buf][32][68]: buf0 [0,2176), buf1 [2176,4352)
//  Wt  [buf][16][68]:  buf0 [4352,5440), buf1 [5440,6528)   (phase1)
//  W2  [buf][ 8][68]:  buf0 [4352,4896), buf1 [4896,5440)   (phase2)
//  red: [6528, 6528+1792)
#define RKC 64
#define RST 68
#define RED_OFF 6528
#define POOLF (RED_OFF + 1792)

__global__ __launch_bounds__(RTHR, 1)
void gru_persistent(const float* __restrict__ H0,
                    const float* __restrict__ Xz, const float* __restrict__ Xr,
                    const float* __restrict__ Xh,
                    const float* __restrict__ WzT, const float* __restrict__ WrT,
                    const float* __restrict__ WhT,
                    float* __restrict__ Hs, float* __restrict__ Z,
                    float* __restrict__ G)
{
    __shared__ float pool[POOLF];

    const int tid = threadIdx.x;
    const int blk = blockIdx.x;
    const int w   = tid >> 5;
    const int b   = tid & 31;          // lane = batch row

    // phase1 mapping: 16 warps = 4 col-groups x 4 k-slices
    const bool isR = blk >= 64;
    const int c1 = (blk & 63) * 16;
    const int p1c4 = w & 3;            // col group (4 cols)
    const int p1kh = w >> 2;           // k slice (16 k of 64)
    const float* __restrict__ W1 = isR ? WrT : WzT;

    // phase2 mapping: 16 warps = 2 col-groups x 8 k-slices
    const int c2 = blk * 8;
    const int p2c4 = w & 1;            // col group (4 cols)
    const int p2kh = w >> 1;           // k slice (8 k of 64)

    for (int t = 0; t < TT; ++t) {
        const float* __restrict__ Hprev = (t == 0) ? H0 : (Hs + (size_t)(t - 1) * BH);
        const float* __restrict__ Xz_t = Xz + (size_t)t * BH;
        const float* __restrict__ Xr_t = Xr + (size_t)t * BH;
        const float* __restrict__ Xh_t = Xh + (size_t)t * BH;
        float* __restrict__ Hnew = Hs + (size_t)t * BH;

        // ---------------- phase 1: Z (blocks 0-63) / R,G (blocks 64-127) ----
        {
            float4 acc[4];
#pragma unroll
            for (int j = 0; j < 4; ++j) acc[j] = make_float4(0.f, 0.f, 0.f, 0.f);

            auto load1 = [&](int buf, int kc) {
                {   // Hp: 32 x 64 = 512 float4, one per thread
                    int row = tid >> 4, q = tid & 15;
                    uint32_t d = smem_u32(&pool[buf * 2176 + row * RST + q * 4]);
                    CP_ASYNC16_CG(d, &Hprev[row * HH + kc + q * 4]);
                }
                if (tid < 256) {  // Wt: 16 x 64 = 256 float4
                    int row = tid >> 4, q = tid & 15;
                    uint32_t d = smem_u32(&pool[4352 + buf * 1088 + row * RST + q * 4]);
                    CP_ASYNC16_CA(d, &W1[(size_t)(c1 + row) * HH + kc + q * 4]);
                }
                CP_COMMIT();
            };

            load1(0, 0);
#pragma unroll 1
            for (int c = 0; c < HH / RKC; ++c) {
                if (c + 1 < HH / RKC) {
                    load1((c + 1) & 1, (c + 1) * RKC);
                    CP_WAIT(1);
                } else {
                    CP_WAIT(0);
                }
                __syncthreads();
                const int buf = c & 1;
                const float* hp = &pool[buf * 2176 + b * RST + p1kh * 16];
                const float* wp = &pool[4352 + buf * 1088 + (p1c4 * 4) * RST + p1kh * 16];
#pragma unroll
                for (int kk = 0; kk < 16; kk += 4) {
                    float4 h = *(const float4*)&hp[kk];
#pragma unroll
                    for (int j = 0; j < 4; ++j) {
                        float4 wj = *(const float4*)&wp[j * RST + kk];
                        acc[j].x += h.x * wj.x; acc[j].y += h.y * wj.y;
                        acc[j].z += h.z * wj.z; acc[j].w += h.w * wj.w;
                    }
                }
                __syncthreads();
            }

            float4 s4;
            s4.x = (acc[0].x + acc[0].y) + (acc[0].z + acc[0].w);
            s4.y = (acc[1].x + acc[1].y) + (acc[1].z + acc[1].w);
            s4.z = (acc[2].x + acc[2].y) + (acc[2].z + acc[2].w);
            s4.w = (acc[3].x + acc[3].y) + (acc[3].z + acc[3].w);

            const int grp = b * 4 + p1c4;   // 0..127
            if (p1kh > 0)
                *(float4*)&pool[RED_OFF + ((p1kh - 1) * 128 + grp) * 4] = s4;
            __syncthreads();
            if (p1kh == 0) {
#pragma unroll
                for (int p = 0; p < 3; ++p) {
                    float4 r = *(const float4*)&pool[RED_OFF + (p * 128 + grp) * 4];
                    s4.x += r.x; s4.y += r.y; s4.z += r.z; s4.w += r.w;
                }
                const int i0 = b * HH + c1 + p1c4 * 4;
                if (!isR) {
                    float4 x = *(const float4*)&Xz_t[i0];
                    float4 zv;
                    zv.x = sigf(x.x + s4.x); zv.y = sigf(x.y + s4.y);
                    zv.z = sigf(x.z + s4.z); zv.w = sigf(x.w + s4.w);
                    __stcg((float4*)&Z[i0], zv);
                } else {
                    float4 x = *(const float4*)&Xr_t[i0];
                    float4 hpv = __ldcg((const float4*)&Hprev[i0]);
                    float4 gv;
                    gv.x = sigf(x.x + s4.x) * hpv.x;
                    gv.y = sigf(x.y + s4.y) * hpv.y;
                    gv.z = sigf(x.z + s4.z) * hpv.z;
                    gv.w = sigf(x.w + s4.w) * hpv.w;
                    __stcg((float4*)&G[i0], gv);
                }
            }
        }

        grid_bar(2 * t);

        // ---------------- phase 2: Hnew --------------------------------------
        {
            float4 acc[4];
#pragma unroll
            for (int j = 0; j < 4; ++j) acc[j] = make_float4(0.f, 0.f, 0.f, 0.f);

            auto load2 = [&](int buf, int kc) {
                {   // Gp: 32 x 64 = 512 float4
                    int row = tid >> 4, q = tid & 15;
                    uint32_t d = smem_u32(&pool[buf * 2176 + row * RST + q * 4]);
                    CP_ASYNC16_CG(d, &G[row * HH + kc + q * 4]);
                }
                if (tid < 128) {  // W2: 8 x 64 = 128 float4
                    int row = tid >> 4, q = tid & 15;
                    uint32_t d = smem_u32(&pool[4352 + buf * 544 + row * RST + q * 4]);
                    CP_ASYNC16_CA(d, &WhT[(size_t)(c2 + row) * HH + kc + q * 4]);
                }
                CP_COMMIT();
            };

            load2(0, 0);
#pragma unroll 1
            for (int c = 0; c < HH / RKC; ++c) {
                if (c + 1 < HH / RKC) {
                    load2((c + 1) & 1, (c + 1) * RKC);
                    CP_WAIT(1);
                } else {
                    CP_WAIT(0);
                }
                __syncthreads();
                const int buf = c & 1;
                const float* gp = &pool[buf * 2176 + b * RST + p2kh * 8];
                const float* wp = &pool[4352 + buf * 544 + (p2c4 * 4) * RST + p2kh * 8];
#pragma unroll
                for (int kk = 0; kk < 8; kk += 4) {
                    float4 g4 = *(const float4*)&gp[kk];
#pragma unroll
                    for (int j = 0; j < 4; ++j) {
                        float4 wj = *(const float4*)&wp[j * RST + kk];
                        acc[j].x += g4.x * wj.x; acc[j].y += g4.y * wj.y;
                        acc[j].z += g4.z * wj.z; acc[j].w += g4.w * wj.w;
                    }
                }
                __syncthreads();
            }

            float4 s4;
            s4.x = (acc[0].x + acc[0].y) + (acc[0].z + acc[0].w);
            s4.y = (acc[1].x + acc[1].y) + (acc[1].z + acc[1].w);
            s4.z = (acc[2].x + acc[2].y) + (acc[2].z + acc[2].w);
            s4.w = (acc[3].x + acc[3].y) + (acc[3].z + acc[3].w);

            const int grp = b * 2 + p2c4;   // 0..63
            if (p2kh > 0)
                *(float4*)&pool[RED_OFF + ((p2kh - 1) * 64 + grp) * 4] = s4;
            __syncthreads();
            if (p2kh == 0) {
#pragma unroll
                for (int p = 0; p < 7; ++p) {
                    float4 r = *(const float4*)&pool[RED_OFF + (p * 64 + grp) * 4];
                    s4.x += r.x; s4.y += r.y; s4.z += r.z; s4.w += r.w;
                }
                const int i0 = b * HH + c2 + p2c4 * 4;
                float4 x = *(const float4*)&Xh_t[i0];
                float4 zv = __ldcg((const float4*)&Z[i0]);
                float4 hpv = __ldcg((const float4*)&Hprev[i0]);
                float4 o;
                o.x = zv.x * hpv.x + (1.f - zv.x) * tanhf(x.x + s4.x);
                o.y = zv.y * hpv.y + (1.f - zv.y) * tanhf(x.y + s4.y);
                o.z = zv.z * hpv.z + (1.f - zv.z) * tanhf(x.z + s4.z);
                o.w = zv.w * hpv.w + (1.f - zv.w) * tanhf(x.w + s4.w);
                __stcg((float4*)&Hnew[i0], o);
            }
        }

        grid_bar(2 * t + 1);
    }
}

// ---------------- H_last copy ----------------------------------------------
__global__ void copy_hlast(const float* __restrict__ src, float* __restrict__ dst)
{
    int i = blockIdx.x * blockDim.x + threadIdx.x;
    if (i < BH) dst[i] = src[i];
}

// ---------------- launch ----------------------------------------------------
extern "C" void kernel_launch(void* const* d_in, const int* in_sizes, int n_in,
                              void* d_out, int out_size)
{
    const float* inputs = (const float*)d_in[0];
    const float* H0     = (const float*)d_in[1];
    const float* W_xz   = (const float*)d_in[2];
    const float* W_hz   = (const float*)d_in[3];
    const float* b_z    = (const float*)d_in[4];
    const float* W_xr   = (const float*)d_in[5];
    const float* W_hr   = (const float*)d_in[6];
    const float* b_r    = (const float*)d_in[7];
    const float* W_xh   = (const float*)d_in[8];
    const float* W_hh   = (const float*)d_in[9];
    const float* b_h    = (const float*)d_in[10];
    const float* W_hq   = (const float*)d_in[11];
    const float* b_q    = (const float*)d_in[12];

    float* out = (float*)d_out;

    float *Xz, *Xr, *Xh, *Hs, *Zb, *Gb, *WzT, *WrT, *WhT;
    cudaGetSymbolAddress((void**)&Xz, g_Xz);
    cudaGetSymbolAddress((void**)&Xr, g_Xr);
    cudaGetSymbolAddress((void**)&Xh, g_Xh);
    cudaGetSymbolAddress((void**)&Hs, g_Hs);
    cudaGetSymbolAddress((void**)&Zb, g_Z);
    cudaGetSymbolAddress((void**)&Gb, g_G);
    cudaGetSymbolAddress((void**)&WzT, g_WzT);
    cudaGetSymbolAddress((void**)&WrT, g_WrT);
    cudaGetSymbolAddress((void**)&WhT, g_WhT);

    // 0) transpose recurrent weights + zero grid-barrier counters
    {
        dim3 tg(32, 32), tb(32, 8);
        transpose1024<<<tg, tb>>>(W_hz, WzT);
        transpose1024<<<tg, tb>>>(W_hr, WrT);
        transpose1024<<<tg, tb>>>(W_hh, WhT);
        bar_init<<<1, 256>>>();
    }

    // 1) input projections (TF32 tensor cores)
    {
        dim3 grid(HH / GBN, M1 / GBM);
        tf32_gemm_bias<<<grid, 256>>>(inputs, W_xz, b_z, Xz, M1, HH, VV);
        tf32_gemm_bias<<<grid, 256>>>(inputs, W_xr, b_r, Xr, M1, HH, VV);
        tf32_gemm_bias<<<grid, 256>>>(inputs, W_xh, b_h, Xh, M1, HH, VV);
    }

    // 2) recurrence: ONE persistent kernel, software grid barriers
    gru_persistent<<<RBLK, RTHR>>>(H0, Xz, Xr, Xh, WzT, WrT, WhT, Hs, Zb, Gb);

    // 3) output projection (TF32)
    {
        dim3 grid((VV + GBN - 1) / GBN, M1 / GBM);
        tf32_gemm_bias<<<grid, 256>>>(Hs, W_hq, b_q, out, M1, VV, HH);
    }

    // 4) H_last appended after outputs if the output buffer includes it
    if (out_size >= M1 * VV + BH) {
        copy_hlast<<<BH / 256, 256>>>(Hs + (size_t)(TT - 1) * BH,
                                      out + (size_t)M1 * VV);
    }
}